// round 5
// baseline (speedup 1.0000x reference)
#include <cuda_runtime.h>

#define NN   50000
#define EE   800000
#define CIN  32
#define COUT 32
#define KEXP 4

// Scratch: y[n][k][c] = map(x[n] @ W[k])[c] as order-preserving uint, 25.6 MB
__device__ unsigned int g_y[NN * KEXP * COUT];

// Monotonic float<->uint mapping: atomicMax on u32 == float max.
__device__ __forceinline__ unsigned int mapFloat(float f) {
    int b = __float_as_int(f);
    return (unsigned int)(b ^ ((b >> 31) | 0x80000000));
}
__device__ __forceinline__ float unmapFloat(unsigned int u) {
    unsigned int b = (u & 0x80000000u) ? (u ^ 0x80000000u) : ~u;
    return __uint_as_float(b);
}
#define MAPPED_NEG_INF 0x007fffffu   // map(-inf)

// ---- packed f32x2 helpers (sm_100a) ----
__device__ __forceinline__ unsigned long long fma2(
    unsigned long long a, unsigned long long b, unsigned long long c) {
    unsigned long long d;
    asm("fma.rn.f32x2 %0, %1, %2, %3;" : "=l"(d) : "l"(a), "l"(b), "l"(c));
    return d;
}
__device__ __forceinline__ unsigned long long packf2(float lo, float hi) {
    unsigned long long d;
    asm("mov.b64 %0, {%1, %2};" : "=l"(d) : "f"(lo), "f"(hi));
    return d;
}
__device__ __forceinline__ void unpackf2(unsigned long long v, float& lo, float& hi) {
    asm("mov.b64 {%0, %1}, %2;" : "=f"(lo), "=f"(hi) : "l"(v));
}

// Thread-per-node GEMM: y[n][k][:] = map(x[n] @ W[k]). Weights broadcast from
// SMEM (1 wavefront per LDS.128); math in packed f32x2. Also inits out rows.
__global__ __launch_bounds__(128) void gemm_kernel(
    const float* __restrict__ x, const float* __restrict__ ew,
    unsigned int* __restrict__ out)
{
    __shared__ float4 sw4[KEXP * CIN * 8];   // raw copy of ew, float4 view
    int tid = threadIdx.x;
    #pragma unroll
    for (int r = 0; r < 8; r++)
        sw4[r * 128 + tid] = ((const float4*)ew)[r * 128 + tid];

    // coalesced init of this block's out span to mapped -inf
    {
        uint4 neg = make_uint4(MAPPED_NEG_INF, MAPPED_NEG_INF, MAPPED_NEG_INF, MAPPED_NEG_INF);
        int start = blockIdx.x * 128 * 8;        // uint4 index (8 per node)
        #pragma unroll
        for (int r = 0; r < 8; r++) {
            int idx = start + r * 128 + tid;
            if (idx < NN * 8) ((uint4*)out)[idx] = neg;
        }
    }
    __syncthreads();

    int n = blockIdx.x * 128 + tid;
    if (n >= NN) return;

    float xv[CIN];
    const float4* xp4 = (const float4*)(x + n * CIN);
    #pragma unroll
    for (int i4 = 0; i4 < 8; i4++) {
        float4 v = xp4[i4];
        xv[i4 * 4] = v.x; xv[i4 * 4 + 1] = v.y; xv[i4 * 4 + 2] = v.z; xv[i4 * 4 + 3] = v.w;
    }
    unsigned long long hp[CIN];
    #pragma unroll
    for (int i = 0; i < CIN; i++) hp[i] = packf2(xv[i], xv[i]);

    const ulonglong2* swp = (const ulonglong2*)sw4;
    unsigned int* yp = &g_y[n * (KEXP * COUT)];

    #pragma unroll
    for (int k = 0; k < KEXP; k++) {
        unsigned long long acc[16];
        #pragma unroll
        for (int t = 0; t < 16; t++) acc[t] = 0ull;
        #pragma unroll
        for (int i = 0; i < CIN; i++) {
            unsigned long long xp = hp[i];
            #pragma unroll
            for (int c4 = 0; c4 < 8; c4++) {
                ulonglong2 w = swp[k * 256 + i * 8 + c4];   // broadcast, 1 wf
                acc[c4 * 2]     = fma2(xp, w.x, acc[c4 * 2]);
                acc[c4 * 2 + 1] = fma2(xp, w.y, acc[c4 * 2 + 1]);
            }
        }
        #pragma unroll
        for (int c4 = 0; c4 < 8; c4++) {
            float f0, f1, f2, f3;
            unpackf2(acc[c4 * 2],     f0, f1);
            unpackf2(acc[c4 * 2 + 1], f2, f3);
            uint4 m = make_uint4(mapFloat(f0), mapFloat(f1), mapFloat(f2), mapFloat(f3));
            ((uint4*)(yp + k * COUT))[c4] = m;
        }
    }
}

// Edge phase: lane-per-edge gate; sweep 4 edges/iter with 8 lanes each:
// one uint4 gather from pre-mapped y + 4 unconditional RED.MAX.U32.
__global__ __launch_bounds__(256) void edge_kernel(
    const float* __restrict__ pos, const int* __restrict__ edge_index,
    const float* __restrict__ gw, const float* __restrict__ gb,
    unsigned int* __restrict__ out)
{
    float g0x = gw[0], g0y = gw[1], g1x = gw[2], g1y = gw[3];
    float g2x = gw[4], g2y = gw[5], g3x = gw[6], g3y = gw[7];
    float b0 = gb[0], b1 = gb[1], b2 = gb[2], b3 = gb[3];

    int tid   = threadIdx.x;
    int lane  = tid & 31;
    int gwarp = (blockIdx.x * blockDim.x + tid) >> 5;
    int nwarp = (gridDim.x * blockDim.x) >> 5;

    int sub = lane >> 3;          // which edge of the quad
    int ch  = (lane & 7) * 4;     // channel base

    for (int base = gwarp * 32; base < EE; base += nwarp * 32) {
        int e = base + lane;                       // EE % 32 == 0
        int2 ei = ((const int2*)edge_index)[e];
        int dst = ei.x, src = ei.y;

        float dx = pos[src * 3]     - pos[dst * 3];
        float dy = pos[src * 3 + 1] - pos[dst * 3 + 1];

        float l0 = fmaf(dx, g0x, fmaf(dy, g0y, b0));
        float l1 = fmaf(dx, g1x, fmaf(dy, g1y, b1));
        float l2 = fmaf(dx, g2x, fmaf(dy, g2y, b2));
        float l3 = fmaf(dx, g3x, fmaf(dy, g3y, b3));
        int bk = 0; float best = l0;
        if (l1 > best) { best = l1; bk = 1; }
        if (l2 > best) { best = l2; bk = 2; }
        if (l3 > best) { best = l3; bk = 3; }

        int yoff = src * (KEXP * COUT) + bk * COUT;
        int doff = dst * COUT;

        #pragma unroll
        for (int j = 0; j < 8; j++) {
            int yo  = __shfl_sync(0xffffffffu, yoff, j * 4 + sub);
            int doo = __shfl_sync(0xffffffffu, doff, j * 4 + sub);
            uint4 m = *(const uint4*)(g_y + yo + ch);   // 128B/edge, L2 hit
            atomicMax(&out[doo + ch + 0], m.x);
            atomicMax(&out[doo + ch + 1], m.y);
            atomicMax(&out[doo + ch + 2], m.z);
            atomicMax(&out[doo + ch + 3], m.w);
        }
    }
}

// MLP: thread-per-node, packed f32x2 math, weights broadcast from SMEM.
__global__ __launch_bounds__(128) void mlp_kernel(
    const float* __restrict__ w1, const float* __restrict__ w2,
    float* __restrict__ outf)
{
    __shared__ float4 s1t[CIN * 16];   // s1t[i*16+j4] = {w1[4j4+k][i]}_{k=0..3}
    __shared__ float4 s2t[64 * 8];     // s2t[j*8 +c4] = {w2[4c4+k][j]}_{k=0..3}
    int tid = threadIdx.x;
    for (int idx = tid; idx < CIN * 16; idx += blockDim.x) {
        int i = idx >> 4, j4 = idx & 15;
        s1t[idx] = make_float4(w1[(j4 * 4 + 0) * 32 + i], w1[(j4 * 4 + 1) * 32 + i],
                               w1[(j4 * 4 + 2) * 32 + i], w1[(j4 * 4 + 3) * 32 + i]);
    }
    for (int idx = tid; idx < 64 * 8; idx += blockDim.x) {
        int j = idx >> 3, c4 = idx & 7;
        s2t[idx] = make_float4(w2[(c4 * 4 + 0) * 64 + j], w2[(c4 * 4 + 1) * 64 + j],
                               w2[(c4 * 4 + 2) * 64 + j], w2[(c4 * 4 + 3) * 64 + j]);
    }
    __syncthreads();

    int n = blockIdx.x * 128 + tid;
    if (n >= NN) return;

    unsigned int* outu = (unsigned int*)outf;
    unsigned long long hp[CIN];   // {h_i, h_i}
    unsigned long long o2[16];    // out channel pairs, init = skip
    const uint4* inp = (const uint4*)(outu + n * COUT);
    #pragma unroll
    for (int i4 = 0; i4 < 8; i4++) {
        uint4 v = inp[i4];
        float f0 = unmapFloat(v.x), f1 = unmapFloat(v.y);
        float f2 = unmapFloat(v.z), f3 = unmapFloat(v.w);
        hp[i4 * 4]     = packf2(f0, f0);
        hp[i4 * 4 + 1] = packf2(f1, f1);
        hp[i4 * 4 + 2] = packf2(f2, f2);
        hp[i4 * 4 + 3] = packf2(f3, f3);
        o2[i4 * 2]     = packf2(f0, f1);
        o2[i4 * 2 + 1] = packf2(f2, f3);
    }

    const ulonglong2* s1p = (const ulonglong2*)s1t;
    const ulonglong2* s2p = (const ulonglong2*)s2t;

    #pragma unroll
    for (int j4 = 0; j4 < 16; j4++) {
        unsigned long long h0 = 0ull, h1 = 0ull;   // {a4j4,a4j4+1},{a4j4+2,a4j4+3}
        #pragma unroll
        for (int i = 0; i < CIN; i++) {
            ulonglong2 w = s1p[i * 16 + j4];
            h0 = fma2(hp[i], w.x, h0);
            h1 = fma2(hp[i], w.y, h1);
        }
        float a0, a1, a2, a3;
        unpackf2(h0, a0, a1); unpackf2(h1, a2, a3);
        a0 = fmaxf(a0, 0.f); a1 = fmaxf(a1, 0.f);
        a2 = fmaxf(a2, 0.f); a3 = fmaxf(a3, 0.f);
        unsigned long long ap0 = packf2(a0, a0), ap1 = packf2(a1, a1);
        unsigned long long ap2 = packf2(a2, a2), ap3 = packf2(a3, a3);
        int j = j4 * 4;
        #pragma unroll
        for (int c4 = 0; c4 < 8; c4++) {
            ulonglong2 wA = s2p[(j + 0) * 8 + c4];
            ulonglong2 wB = s2p[(j + 1) * 8 + c4];
            ulonglong2 wC = s2p[(j + 2) * 8 + c4];
            ulonglong2 wD = s2p[(j + 3) * 8 + c4];
            unsigned long long lo = o2[c4 * 2], hi = o2[c4 * 2 + 1];
            lo = fma2(ap0, wA.x, lo); hi = fma2(ap0, wA.y, hi);
            lo = fma2(ap1, wB.x, lo); hi = fma2(ap1, wB.y, hi);
            lo = fma2(ap2, wC.x, lo); hi = fma2(ap2, wC.y, hi);
            lo = fma2(ap3, wD.x, lo); hi = fma2(ap3, wD.y, hi);
            o2[c4 * 2] = lo; o2[c4 * 2 + 1] = hi;
        }
    }

    float4* op = (float4*)(outf + n * COUT);
    #pragma unroll
    for (int c4 = 0; c4 < 8; c4++) {
        float f0, f1, f2, f3;
        unpackf2(o2[c4 * 2],     f0, f1);
        unpackf2(o2[c4 * 2 + 1], f2, f3);
        op[c4] = make_float4(f0, f1, f2, f3);
    }
}

extern "C" void kernel_launch(void* const* d_in, const int* in_sizes, int n_in,
                              void* d_out, int out_size) {
    const float* x          = (const float*)d_in[0];
    const float* pos        = (const float*)d_in[1];
    const int*   edge_index = (const int*)  d_in[2];
    const float* ew         = (const float*)d_in[3];
    const float* gw         = (const float*)d_in[4];
    const float* gb         = (const float*)d_in[5];
    const float* w1         = (const float*)d_in[6];
    const float* w2         = (const float*)d_in[7];

    gemm_kernel<<<(NN + 127) / 128, 128>>>(x, ew, (unsigned int*)d_out);
    edge_kernel<<<2048, 256>>>(pos, edge_index, gw, gb, (unsigned int*)d_out);
    mlp_kernel<<<(NN + 127) / 128, 128>>>(w1, w2, (float*)d_out);
}